// round 6
// baseline (speedup 1.0000x reference)
#include <cuda_runtime.h>
#include <math.h>
#include <stdint.h>

// Problem constants (fixed shapes from reference)
#define N_SEL   200000
#define NEV     100000     // E
#define MEMD    100
#define RAWD    172
#define TDD     100
#define MSGD    472        // 2*MEM + RAW + TD
#define KI      480        // MSGD padded to multiple of 16
#define KH      112        // MEM padded to multiple of 16
#define NCH     300        // 3*MEM gate channels
#define NCP     320        // padded channels
#define BM      128
#define BN      64
#define BK      16
#define MROWS   200064     // 1563 * 128 (grid-covered row count)

// ---------------- device scratch (allocation-free: __device__ globals) ------
__device__ unsigned long long g_best[N_SEL];
__device__ int   g_slot[N_SEL];
__device__ int   g_nvalid;
__device__ float g_Wi[NCP * KI];                 // padded W_ih  [320][480]
__device__ float g_Wh[NCP * KH];                 // padded W_hh  [320][112]
__device__ float g_msg[(size_t)MROWS * KI];      // compacted messages
__device__ float g_h  [(size_t)MROWS * KH];      // gathered h rows (padded)
__device__ float g_gi [(size_t)MROWS * NCP];     // MSG @ W_ih^T
__device__ float g_gh [(size_t)MROWS * NCP];     // H   @ W_hh^T

// ---------------- 1) init: reset state, build padded weight tiles ----------
__global__ void k_init(const float* __restrict__ Wih, const float* __restrict__ Whh) {
    int stride = gridDim.x * blockDim.x;
    int tid = blockIdx.x * blockDim.x + threadIdx.x;
    if (tid == 0) g_nvalid = 0;
    for (int i = tid; i < N_SEL; i += stride) g_best[i] = 0ull;
    for (int i = tid; i < NCP * KI; i += stride) {
        int c = i / KI, k = i - c * KI;
        g_Wi[i] = (c < NCH && k < MSGD) ? Wih[c * MSGD + k] : 0.f;
    }
    for (int i = tid; i < NCP * KH; i += stride) {
        int c = i / KH, k = i - c * KH;
        g_Wh[i] = (c < NCH && k < MEMD) ? Whh[c * MEMD + k] : 0.f;
    }
}

// ---------------- 2) scatter argmax(t, eidx) per local node ----------------
__global__ void k_scatter(const int* __restrict__ loc_s, const int* __restrict__ t_s,
                          const int* __restrict__ loc_d, const int* __restrict__ t_d) {
    int e = blockIdx.x * blockDim.x + threadIdx.x;
    if (e < NEV) {
        unsigned long long key =
            ((unsigned long long)(unsigned)(t_s[e] + 1) << 32) | (unsigned)e;
        atomicMax(&g_best[loc_s[e]], key);
    } else if (e < 2 * NEV) {
        int i = e - NEV;
        unsigned long long key =
            ((unsigned long long)(unsigned)(t_d[i] + 1) << 32) | (unsigned)e;
        atomicMax(&g_best[loc_d[i]], key);
    }
}

// ---------------- 3) compact valid nodes (warp-aggregated) -----------------
__global__ void k_slots() {
    int i = blockIdx.x * blockDim.x + threadIdx.x;
    bool valid = (i < N_SEL) && (g_best[i] != 0ull);
    unsigned mask = __ballot_sync(0xffffffffu, valid);
    int slot = -1;
    if (valid) {
        int lane = threadIdx.x & 31;
        int leader = __ffs(mask) - 1;
        int base = 0;
        if (lane == leader) base = atomicAdd(&g_nvalid, __popc(mask));
        base = __shfl_sync(mask, base, leader);
        slot = base + __popc(mask & ((1u << lane) - 1u));
    }
    if (i < N_SEL) g_slot[i] = slot;
}

// ---------------- 4) gather h, build msg row, write new_last_update --------
__global__ void k_build(const float* __restrict__ memory, const int* __restrict__ last_update,
                        const int* __restrict__ n_id,
                        const int* __restrict__ dst_s, const float* __restrict__ raw_s,
                        const int* __restrict__ dst_d, const float* __restrict__ raw_d,
                        const float* __restrict__ tw, const float* __restrict__ tb,
                        float* __restrict__ out, int out_size) {
    int i = blockIdx.x;
    int tid = threadIdx.x;
    __shared__ int s_slot, s_e, s_t;
    int gid = n_id[i];
    int lu = last_update[gid];
    if (tid == 0) {
        unsigned long long key = g_best[i];
        int slot = g_slot[i], e = 0, t = 0;
        if (key != 0ull) {
            e = (int)(key & 0xffffffffull);
            t = (int)(key >> 32) - 1;
        }
        s_slot = slot; s_e = e; s_t = t;
        // new_last_update = max(last_update[gid], best t among this node's events)
        int nlu = (key != 0ull && t > lu) ? t : lu;
        if (out_size >= N_SEL * MEMD + N_SEL)
            out[(size_t)N_SEL * MEMD + i] = (float)nlu;
    }
    __syncthreads();
    // h row (zero padded to KH)
    const float* hrow = memory + (size_t)gid * MEMD;
    float* hd = g_h + (size_t)i * KH;
    for (int k = tid; k < KH; k += 128) hd[k] = (k < MEMD) ? hrow[k] : 0.f;

    int slot = s_slot;
    if (slot < 0) return;
    int e = s_e, t = s_t;
    int dst = (e < NEV) ? dst_s[e] : dst_d[e - NEV];
    const float* raw = (e < NEV) ? (raw_s + (size_t)e * RAWD)
                                 : (raw_d + (size_t)(e - NEV) * RAWD);
    const float* drow = memory + (size_t)dst * MEMD;
    float trel = (float)(t - lu);
    float* m = g_msg + (size_t)slot * KI;
    for (int k = tid; k < KI; k += 128) {
        float v;
        if (k < MEMD)             v = hrow[k];                 // memory[src] == h
        else if (k < 2 * MEMD)    v = drow[k - MEMD];          // memory[dst]
        else if (k < 2 * MEMD + RAWD) v = raw[k - 2 * MEMD];   // raw_msg
        else if (k < MSGD) {                                   // time encoding
            int j = k - (2 * MEMD + RAWD);
            // match jnp: fp32 mul then fp32 add (no fma), accurate cos
            float arg = __fadd_rn(__fmul_rn(trel, tw[j]), tb[j]);
            v = (float)cos((double)arg);
        } else v = 0.f;
        m[k] = v;
    }
}

// ---------------- 5) SGEMM: C[m][c] = sum_k A[m][k] * B[c][k] --------------
// MODE 0: g_gi = g_msg @ g_Wi^T   (rows bounded by g_nvalid)
// MODE 1: g_gh = g_h   @ g_Wh^T   (all MROWS rows)
template <int MODE>
__global__ void __launch_bounds__(256) k_sgemm() {
    constexpr int LDA = (MODE == 0) ? KI : KH;
    const float* __restrict__ A = (MODE == 0) ? g_msg : g_h;
    const float* __restrict__ B = (MODE == 0) ? g_Wi  : g_Wh;
    float* __restrict__ C       = (MODE == 0) ? g_gi  : g_gh;

    int mbase = blockIdx.x * BM;
    if (MODE == 0 && mbase >= g_nvalid) return;
    int nbase = blockIdx.y * BN;

    __shared__ float As[BK][BM + 4];
    __shared__ float Bs[BK][BN + 4];
    int tid = threadIdx.x;
    int tm = tid >> 4;        // 0..15 -> 8 M rows
    int tn = tid & 15;        // 0..15 -> 4 N cols

    float acc[8][4];
#pragma unroll
    for (int x = 0; x < 8; x++)
#pragma unroll
        for (int y = 0; y < 4; y++) acc[x][y] = 0.f;

    const float* Ab = A + (size_t)mbase * LDA;
    const float* Bb = B + (size_t)nbase * LDA;

    for (int kt = 0; kt < LDA; kt += BK) {
#pragma unroll
        for (int i = 0; i < 2; i++) {
            int lin = tid + i * 256;              // 512 float4 = 128 rows x 16 k
            int m = lin >> 2;
            int k4 = (lin & 3) << 2;
            float4 v = *(const float4*)(Ab + (size_t)m * LDA + kt + k4);
            As[k4 + 0][m] = v.x; As[k4 + 1][m] = v.y;
            As[k4 + 2][m] = v.z; As[k4 + 3][m] = v.w;
        }
        {
            int n = tid >> 2;                     // 256 float4 = 64 rows x 16 k
            int k4 = (tid & 3) << 2;
            float4 v = *(const float4*)(Bb + (size_t)n * LDA + kt + k4);
            Bs[k4 + 0][n] = v.x; Bs[k4 + 1][n] = v.y;
            Bs[k4 + 2][n] = v.z; Bs[k4 + 3][n] = v.w;
        }
        __syncthreads();
#pragma unroll
        for (int kk = 0; kk < BK; kk++) {
            float4 a0 = *(const float4*)&As[kk][tm * 8];
            float4 a1 = *(const float4*)&As[kk][tm * 8 + 4];
            float4 bv = *(const float4*)&Bs[kk][tn * 4];
            float a[8] = {a0.x, a0.y, a0.z, a0.w, a1.x, a1.y, a1.z, a1.w};
            float b[4] = {bv.x, bv.y, bv.z, bv.w};
#pragma unroll
            for (int x = 0; x < 8; x++)
#pragma unroll
                for (int y = 0; y < 4; y++)
                    acc[x][y] += a[x] * b[y];
        }
        __syncthreads();
    }
    float* Cb = C + (size_t)mbase * NCP + nbase;
#pragma unroll
    for (int x = 0; x < 8; x++) {
        int m = tm * 8 + x;
        float4 o = make_float4(acc[x][0], acc[x][1], acc[x][2], acc[x][3]);
        *(float4*)(Cb + (size_t)m * NCP + tn * 4) = o;
    }
}

// ---------------- 6) GRU epilogue ------------------------------------------
__global__ void k_gru(const float* __restrict__ bih, const float* __restrict__ bhh,
                      float* __restrict__ out) {
    int idx = blockIdx.x * blockDim.x + threadIdx.x;
    if (idx >= N_SEL * MEMD) return;
    int i = idx / MEMD, j = idx - i * MEMD;
    int s = g_slot[i];
    float gir = 0.f, giz = 0.f, gin = 0.f;
    if (s >= 0) {
        const float* g = g_gi + (size_t)s * NCP;
        gir = g[j]; giz = g[j + 100]; gin = g[j + 200];
    }
    const float* gh = g_gh + (size_t)i * NCP;
    float hr = gh[j]       + bhh[j];
    float hz = gh[j + 100] + bhh[j + 100];
    float hn = gh[j + 200] + bhh[j + 200];
    float r = 1.f / (1.f + expf(-(gir + bih[j]       + hr)));
    float z = 1.f / (1.f + expf(-(giz + bih[j + 100] + hz)));
    float n = tanhf(gin + bih[j + 200] + r * hn);
    float h = g_h[(size_t)i * KH + j];
    out[idx] = (1.f - z) * n + z * h;
}

__global__ void k_tail_zero(float* __restrict__ out, int lo, int hi) {
    int idx = lo + blockIdx.x * blockDim.x + threadIdx.x;
    if (idx < hi) out[idx] = 0.f;
}

// ---------------- launch ----------------------------------------------------
extern "C" void kernel_launch(void* const* d_in, const int* in_sizes, int n_in,
                              void* d_out, int out_size) {
    const float* memory      = (const float*)d_in[0];
    const int*   last_update = (const int*)  d_in[1];
    const int*   n_id        = (const int*)  d_in[2];
    const int*   loc_s       = (const int*)  d_in[3];
    const int*   dst_s       = (const int*)  d_in[4];
    const int*   t_s         = (const int*)  d_in[5];
    const float* raw_s       = (const float*)d_in[6];
    const int*   loc_d       = (const int*)  d_in[7];
    const int*   dst_d       = (const int*)  d_in[8];
    const int*   t_d         = (const int*)  d_in[9];
    const float* raw_d       = (const float*)d_in[10];
    const float* tw          = (const float*)d_in[11];
    const float* tb          = (const float*)d_in[12];
    const float* Wih         = (const float*)d_in[13];
    const float* Whh         = (const float*)d_in[14];
    const float* bih         = (const float*)d_in[15];
    const float* bhh         = (const float*)d_in[16];
    float* out = (float*)d_out;

    k_init<<<400, 256>>>(Wih, Whh);
    k_scatter<<<(2 * NEV + 255) / 256, 256>>>(loc_s, t_s, loc_d, t_d);
    k_slots<<<(N_SEL + 255) / 256, 256>>>();
    k_build<<<N_SEL, 128>>>(memory, last_update, n_id, dst_s, raw_s,
                            dst_d, raw_d, tw, tb, out, out_size);
    dim3 gg(MROWS / BM, NCP / BN);   // 1563 x 5
    k_sgemm<0><<<gg, 256>>>();
    k_sgemm<1><<<gg, 256>>>();
    k_gru<<<(N_SEL * MEMD + 255) / 256, 256>>>(bih, bhh, out);

    int written = N_SEL * MEMD + ((out_size >= N_SEL * MEMD + N_SEL) ? N_SEL : 0);
    if (out_size > written) {
        int rem = out_size - written;
        k_tail_zero<<<(rem + 255) / 256, 256>>>(out, written, out_size);
    }
}

// round 9
// speedup vs baseline: 1.7158x; 1.7158x over previous
#include <cuda_runtime.h>
#include <cuda_bf16.h>
#include <math.h>
#include <stdint.h>

// ---------------- problem constants ----------------
#define N_SEL   200000
#define NEV     100000
#define MEMD    100
#define RAWD    172
#define MSGD    472
#define KC      576            // 472 msg + 100 h + 4 pad (9 chunks of 64)
#define NKCH    9
#define BM      128
#define BNT     13             // n8 tiles per gate tile (104 cols, 100 live)
#define BN      104
#define GSTRIDE 416            // 4 gates * 104
#define NTILES  1563
#define MROWS   (NTILES * BM)  // 200064
#define ASTRIDE 72             // smem row stride (bf16 elems), conflict-free

// ---------------- device scratch (allocation-free) ----------------
__device__ unsigned long long g_best[N_SEL];
__device__ __align__(16) __nv_bfloat16 g_Ah[(size_t)MROWS * KC];
__device__ __align__(16) __nv_bfloat16 g_Al[(size_t)MROWS * KC];
__device__ __align__(16) __nv_bfloat16 g_Bh[4 * BN * KC];
__device__ __align__(16) __nv_bfloat16 g_Bl[4 * BN * KC];
__device__ __align__(16) float g_G[(size_t)MROWS * GSTRIDE];

// ---------------- helpers ----------------
__device__ __forceinline__ uint32_t smem_u32(const void* p) {
    uint32_t a;
    asm("{ .reg .u64 t; cvta.to.shared.u64 t, %1; cvt.u32.u64 %0, t; }" : "=r"(a) : "l"(p));
    return a;
}
#define CP16(dst, src) \
    asm volatile("cp.async.cg.shared.global [%0], [%1], 16;" :: "r"(dst), "l"(src) : "memory")
#define CP_COMMIT() asm volatile("cp.async.commit_group;" ::: "memory")

#define MMA(c, a0, a1, a2, a3, b0, b1) \
    asm volatile( \
        "mma.sync.aligned.m16n8k16.row.col.f32.bf16.bf16.f32 " \
        "{%0,%1,%2,%3}, {%4,%5,%6,%7}, {%8,%9}, {%0,%1,%2,%3};" \
        : "+f"((c)[0]), "+f"((c)[1]), "+f"((c)[2]), "+f"((c)[3]) \
        : "r"(a0), "r"(a1), "r"(a2), "r"(a3), "r"(b0), "r"(b1))

// ---------------- 1) init: zero g_best, build fused bf16 hi/lo weights -------
// g_B*[gate][n][k]: n = output channel j (0..99, pad to 104), k in fused dim:
//   gate 0 (r):  k<472: Wih[j][k]         ; 472<=k<572: Whh[j][k-472]
//   gate 1 (z):  k<472: Wih[100+j][k]     ; 472<=k<572: Whh[100+j][k-472]
//   gate 2 (in): k<472: Wih[200+j][k]     ; else 0
//   gate 3 (hn): 472<=k<572: Whh[200+j][k-472] ; else 0
__global__ void k_init(const float* __restrict__ Wih, const float* __restrict__ Whh) {
    int stride = gridDim.x * blockDim.x;
    int t0 = blockIdx.x * blockDim.x + threadIdx.x;
    for (int i = t0; i < N_SEL; i += stride) g_best[i] = 0ull;
    const int TOT = 4 * BN * KC;
    for (int i = t0; i < TOT; i += stride) {
        int gate = i / (BN * KC);
        int rem  = i - gate * (BN * KC);
        int n = rem / KC, k = rem - n * KC;
        float wv = 0.f;
        if (n < 100) {
            if (gate == 0) {
                if (k < MSGD)                 wv = Wih[n * MSGD + k];
                else if (k < MSGD + MEMD)     wv = Whh[n * MEMD + (k - MSGD)];
            } else if (gate == 1) {
                if (k < MSGD)                 wv = Wih[(100 + n) * MSGD + k];
                else if (k < MSGD + MEMD)     wv = Whh[(100 + n) * MEMD + (k - MSGD)];
            } else if (gate == 2) {
                if (k < MSGD)                 wv = Wih[(200 + n) * MSGD + k];
            } else {
                if (k >= MSGD && k < MSGD + MEMD) wv = Whh[(200 + n) * MEMD + (k - MSGD)];
            }
        }
        __nv_bfloat16 hi = __float2bfloat16(wv);
        __nv_bfloat16 lo = __float2bfloat16(wv - __bfloat162float(hi));
        g_Bh[i] = hi;
        g_Bl[i] = lo;
    }
}

// ---------------- 2) scatter argmax(t, eidx) per local node ----------------
__global__ void k_scatter(const int* __restrict__ loc_s, const int* __restrict__ t_s,
                          const int* __restrict__ loc_d, const int* __restrict__ t_d) {
    int e = blockIdx.x * blockDim.x + threadIdx.x;
    if (e < NEV) {
        unsigned long long key =
            ((unsigned long long)(unsigned)(t_s[e] + 1) << 32) | (unsigned)e;
        atomicMax(&g_best[loc_s[e]], key);
    } else if (e < 2 * NEV) {
        int i = e - NEV;
        unsigned long long key =
            ((unsigned long long)(unsigned)(t_d[i] + 1) << 32) | (unsigned)e;
        atomicMax(&g_best[loc_d[i]], key);
    }
}

// ---------------- time encoder: fp32 arg (mul+add like ref), CW + __cosf ------
__device__ __forceinline__ float tenc(float trel, float w, float b) {
    float arg = __fadd_rn(__fmul_rn(trel, w), b);
    float k = rintf(arg * 0.15915494309189535f);
    float r = __fmaf_rn(-k, 6.2831854820251465f, arg);   // fp32(2*pi)
    r = __fmaf_rn(-k, -1.7484555e-7f, r);                // 2*pi - fp32(2*pi)
    return __cosf(r);
}

// store 4 fp32 as bf16 hi/lo pairs at float4-chunk index c4
__device__ __forceinline__ void st_split(__nv_bfloat16* __restrict__ Ah,
                                         __nv_bfloat16* __restrict__ Al,
                                         int c4, float4 v) {
    union { __nv_bfloat162 q[2]; uint2 u; } H, L;
    H.q[0] = __float22bfloat162_rn(make_float2(v.x, v.y));
    H.q[1] = __float22bfloat162_rn(make_float2(v.z, v.w));
    float2 f0 = __bfloat1622float2(H.q[0]);
    float2 f1 = __bfloat1622float2(H.q[1]);
    L.q[0] = __float22bfloat162_rn(make_float2(v.x - f0.x, v.y - f0.y));
    L.q[1] = __float22bfloat162_rn(make_float2(v.z - f1.x, v.w - f1.y));
    *(uint2*)(Ah + c4 * 4) = H.u;
    *(uint2*)(Al + c4 * 4) = L.u;
}

// ---------------- 3) build fused A rows (warp per node) + new_last_update ----
__global__ void k_build(const float* __restrict__ memory, const int* __restrict__ last_update,
                        const int* __restrict__ n_id,
                        const int* __restrict__ dst_s, const float* __restrict__ raw_s,
                        const int* __restrict__ dst_d, const float* __restrict__ raw_d,
                        const float* __restrict__ tw, const float* __restrict__ tb,
                        float* __restrict__ out, int out_size) {
    int w = (blockIdx.x * blockDim.x + threadIdx.x) >> 5;
    int lane = threadIdx.x & 31;
    if (w >= N_SEL) return;
    int gid = __ldg(n_id + w);
    int lu  = __ldg(last_update + gid);
    unsigned long long key = g_best[w];
    __nv_bfloat16* Ah = g_Ah + (size_t)w * KC;
    __nv_bfloat16* Al = g_Al + (size_t)w * KC;
    const float4* hsrc = (const float4*)(memory + (size_t)gid * MEMD);
    // h block: cols 472..575 (c4 118..143; 25 data float4 + 1 zero pad)
    if (lane < 26) {
        float4 v = make_float4(0.f, 0.f, 0.f, 0.f);
        if (lane < 25) v = __ldg(hsrc + lane);
        st_split(Ah, Al, 118 + lane, v);
    }
    bool wlast = (out_size >= N_SEL * MEMD + N_SEL);
    if (key == 0ull) {
        uint2 z = make_uint2(0u, 0u);
        for (int c = lane; c < 118; c += 32) {
            *(uint2*)(Ah + c * 4) = z;
            *(uint2*)(Al + c * 4) = z;
        }
        if (lane == 0 && wlast) out[(size_t)N_SEL * MEMD + w] = (float)lu;
        return;
    }
    int e = (int)(key & 0xffffffffull);
    int t = (int)(key >> 32) - 1;
    if (lane == 0 && wlast) out[(size_t)N_SEL * MEMD + w] = (float)(t > lu ? t : lu);
    int dst; const float* raw;
    if (e < NEV) { dst = __ldg(dst_s + e); raw = raw_s + (size_t)e * RAWD; }
    else { int e2 = e - NEV; dst = __ldg(dst_d + e2); raw = raw_d + (size_t)e2 * RAWD; }
    const float4* dsrc = (const float4*)(memory + (size_t)dst * MEMD);
    const float4* rsrc = (const float4*)raw;
    float trel = (float)(t - lu);
    for (int c = lane; c < 118; c += 32) {
        float4 v;
        if (c < 25)      v = __ldg(hsrc + c);            // memory[src] == h
        else if (c < 50) v = __ldg(dsrc + (c - 25));     // memory[dst]
        else if (c < 93) v = __ldg(rsrc + (c - 50));     // raw_msg
        else {
            int j = (c - 93) << 2;                       // time encoding
            v.x = tenc(trel, __ldg(tw + j),     __ldg(tb + j));
            v.y = tenc(trel, __ldg(tw + j + 1), __ldg(tb + j + 1));
            v.z = tenc(trel, __ldg(tw + j + 2), __ldg(tb + j + 2));
            v.w = tenc(trel, __ldg(tw + j + 3), __ldg(tb + j + 3));
        }
        st_split(Ah, Al, c, v);
    }
}

// ---------------- 4) bf16 split-3 mma.sync GEMM -> g_G ----------------------
// Per-CTA: 128 rows x 104 cols (one gate), K=576 in 9 chunks of 64,
// cp.async double buffered. smem per buffer: Ah/Al 128x72, Bh/Bl 104x72.
#define SM_AH   0
#define SM_AL   18432
#define SM_BH   36864
#define SM_BL   51840
#define SM_BUF  66816
#define SM_TOT  (2 * SM_BUF)   // 133632

__device__ __forceinline__ void mma_issue_chunk(int kc, int buf, uint32_t sb,
                                                int mbase,
                                                const __nv_bfloat16* __restrict__ gBh,
                                                const __nv_bfloat16* __restrict__ gBl,
                                                int tid) {
    uint32_t base = sb + buf * SM_BUF;
    int koff = kc * 64;
#pragma unroll
    for (int it = 0; it < 4; it++) {
        int idx = tid + it * 256;                 // 1024 = 128 rows x 8 (16B) chunks
        int r = idx >> 3, c = idx & 7;
        uint32_t d = base + r * 144 + c * 16;
        const __nv_bfloat16* s = g_Ah + (size_t)(mbase + r) * KC + koff + c * 8;
        CP16(d + SM_AH, s);
        const __nv_bfloat16* s2 = g_Al + (size_t)(mbase + r) * KC + koff + c * 8;
        CP16(d + SM_AL, s2);
    }
    for (int idx = tid; idx < 832; idx += 256) {  // 104 rows x 8 chunks
        int n = idx >> 3, c = idx & 7;
        uint32_t d = base + n * 144 + c * 16;
        CP16(d + SM_BH, gBh + (size_t)n * KC + koff + c * 8);
        CP16(d + SM_BL, gBl + (size_t)n * KC + koff + c * 8);
    }
    CP_COMMIT();
}

__global__ void __launch_bounds__(256) k_mma() {
    extern __shared__ __align__(16) char smem[];
    uint32_t sb = smem_u32(smem);
    int tid = threadIdx.x;
    int wid = tid >> 5, lane = tid & 31;
    int gid = lane >> 2, tig = lane & 3;
    int mbase = blockIdx.x * BM;
    int gate = blockIdx.y;
    const __nv_bfloat16* gBh = g_Bh + (size_t)gate * BN * KC;
    const __nv_bfloat16* gBl = g_Bl + (size_t)gate * BN * KC;

    float acc[BNT][4];
#pragma unroll
    for (int nt = 0; nt < BNT; nt++)
#pragma unroll
        for (int q = 0; q < 4; q++) acc[nt][q] = 0.f;

    mma_issue_chunk(0, 0, sb, mbase, gBh, gBl, tid);

    for (int kc = 0; kc < NKCH; kc++) {
        int buf = kc & 1;
        if (kc + 1 < NKCH) {
            mma_issue_chunk(kc + 1, buf ^ 1, sb, mbase, gBh, gBl, tid);
            asm volatile("cp.async.wait_group 1;" ::: "memory");
        } else {
            asm volatile("cp.async.wait_group 0;" ::: "memory");
        }
        __syncthreads();

        const char* cb = smem + buf * SM_BUF;
        const __nv_bfloat16* Ah = (const __nv_bfloat16*)(cb + SM_AH);
        const __nv_bfloat16* Al = (const __nv_bfloat16*)(cb + SM_AL);
        const __nv_bfloat16* Bh = (const __nv_bfloat16*)(cb + SM_BH);
        const __nv_bfloat16* Bl = (const __nv_bfloat16*)(cb + SM_BL);
        int abase = (wid * 16 + gid) * ASTRIDE;
#pragma unroll
        for (int ks = 0; ks < 4; ks++) {
            int ao = abase + ks * 16 + tig * 2;
            uint32_t ah0 = *(const uint32_t*)(Ah + ao);
            uint32_t ah1 = *(const uint32_t*)(Ah + ao + 8 * ASTRIDE);
            uint32_t ah2 = *(const uint32_t*)(Ah + ao + 8);
            uint32_t ah3 = *(const uint32_t*)(Ah + ao + 8 * ASTRIDE + 8);
            uint32_t al0 = *(const uint32_t*)(Al + ao);
            uint32_t al1 = *(const uint32_t*)(Al + ao + 8 * ASTRIDE);
            uint32_t al2 = *(const uint32_t*)(Al + ao + 8);
            uint32_t al3 = *(const uint32_t*)(Al + ao + 8 * ASTRIDE + 8);
            int bo = gid * ASTRIDE + ks * 16 + tig * 2;
#pragma unroll
            for (int nt = 0; nt < BNT; nt++) {     // Ah * Bh
                uint32_t b0 = *(const uint32_t*)(Bh + bo + nt * 8 * ASTRIDE);
                uint32_t b1 = *(const uint32_t*)(Bh + bo + nt * 8 * ASTRIDE + 8);
                MMA(acc[nt], ah0, ah1, ah2, ah3, b0, b1);
            }
#pragma unroll
            for (int nt = 0; nt < BNT; nt++) {     // Ah * Bl
                uint32_t b0 = *(const uint32_t*)(Bl + bo + nt * 8 * ASTRIDE);
                uint32_t b1 = *(const uint32_t*)(Bl + bo + nt * 8 * ASTRIDE + 8);
                MMA(acc[nt], ah0, ah1, ah2, ah3, b0, b1);
            }
#pragma unroll
            for (int nt = 0; nt < BNT; nt++) {     // Al * Bh
                uint32_t b0 = *(const uint32_t*)(Bh + bo + nt * 8 * ASTRIDE);
                uint32_t b1 = *(const uint32_t*)(Bh + bo + nt * 8 * ASTRIDE + 8);
                MMA(acc[nt], al0, al1, al2, al3, b0, b1);
            }
        }
        __syncthreads();
    }

    // write gate plane: D[gid][tig*2(+1)] rows wid*16+gid / +8
    size_t r0 = (size_t)mbase + wid * 16 + gid;
    size_t r1 = r0 + 8;
    int colb = gate * BN + tig * 2;
#pragma unroll
    for (int nt = 0; nt < BNT; nt++) {
        *(float2*)&g_G[r0 * GSTRIDE + colb + nt * 8] = make_float2(acc[nt][0], acc[nt][1]);
        *(float2*)&g_G[r1 * GSTRIDE + colb + nt * 8] = make_float2(acc[nt][2], acc[nt][3]);
    }
}

// ---------------- 5) GRU epilogue ------------------------------------------
__global__ void k_gru(const float* __restrict__ memory, const int* __restrict__ n_id,
                      const float* __restrict__ bih, const float* __restrict__ bhh,
                      float* __restrict__ out) {
    int idx = blockIdx.x * blockDim.x + threadIdx.x;
    if (idx >= N_SEL * MEMD) return;
    int i = idx / MEMD, j = idx - i * MEMD;
    const float* G = g_G + (size_t)i * GSTRIDE;
    float gr  = G[j];
    float gz  = G[BN + j];
    float gin = G[2 * BN + j];
    float ghn = G[3 * BN + j];
    float h = __ldg(memory + (size_t)__ldg(n_id + i) * MEMD + j);
    float r = 1.f / (1.f + expf(-(gr + __ldg(bih + j) + __ldg(bhh + j))));
    float z = 1.f / (1.f + expf(-(gz + __ldg(bih + 100 + j) + __ldg(bhh + 100 + j))));
    float n = tanhf(gin + __ldg(bih + 200 + j) + r * (ghn + __ldg(bhh + 200 + j)));
    out[idx] = (1.f - z) * n + z * h;
}

__global__ void k_tail_zero(float* __restrict__ out, int lo, int hi) {
    int idx = lo + blockIdx.x * blockDim.x + threadIdx.x;
    if (idx < hi) out[idx] = 0.f;
}

// ---------------- launch ----------------------------------------------------
extern "C" void kernel_launch(void* const* d_in, const int* in_sizes, int n_in,
                              void* d_out, int out_size) {
    const float* memory      = (const float*)d_in[0];
    const int*   last_update = (const int*)  d_in[1];
    const int*   n_id        = (const int*)  d_in[2];
    const int*   loc_s       = (const int*)  d_in[3];
    const int*   dst_s       = (const int*)  d_in[4];
    const int*   t_s         = (const int*)  d_in[5];
    const float* raw_s       = (const float*)d_in[6];
    const int*   loc_d       = (const int*)  d_in[7];
    const int*   dst_d       = (const int*)  d_in[8];
    const int*   t_d         = (const int*)  d_in[9];
    const float* raw_d       = (const float*)d_in[10];
    const float* tw          = (const float*)d_in[11];
    const float* tb          = (const float*)d_in[12];
    const float* Wih         = (const float*)d_in[13];
    const float* Whh         = (const float*)d_in[14];
    const float* bih         = (const float*)d_in[15];
    const float* bhh         = (const float*)d_in[16];
    float* out = (float*)d_out;

    static int smem_set = 0;
    if (!smem_set) {
        cudaFuncSetAttribute(k_mma, cudaFuncAttributeMaxDynamicSharedMemorySize, SM_TOT);
        smem_set = 1;
    }

    k_init<<<512, 256>>>(Wih, Whh);
    k_scatter<<<(2 * NEV + 255) / 256, 256>>>(loc_s, t_s, loc_d, t_d);
    k_build<<<N_SEL / 8, 256>>>(memory, last_update, n_id, dst_s, raw_s,
                                dst_d, raw_d, tw, tb, out, out_size);
    dim3 gg(NTILES, 4);
    k_mma<<<gg, 256, SM_TOT>>>();
    k_gru<<<(N_SEL * MEMD + 255) / 256, 256>>>(memory, n_id, bih, bhh, out);

    int written = N_SEL * MEMD + ((out_size >= N_SEL * MEMD + N_SEL) ? N_SEL : 0);
    if (out_size > written) {
        int rem = out_size - written;
        k_tail_zero<<<(rem + 255) / 256, 256>>>(out, written, out_size);
    }
}